// round 7
// baseline (speedup 1.0000x reference)
#include <cuda_runtime.h>
#include <cuda_fp16.h>
#include <math.h>
#include <stdint.h>

// ---------------------------------------------------------------------------
// SingleHeadAttention via fp16 mma.sync (m16n8k16) + ldmatrix, fp32 accum.
// 3-stage cp.async pipeline, single __syncthreads per k-iteration.
//   conv:   X, W -> fp16 copies (2 launches)
//   stage1: q/k/v projections (z in {0,1,2}); q,k fp16 row-major + V^T fp16
//   stage2: scores GEMM; epilogue: e = mask?0:exp(s*scale-6) -> fp16 P
//   rowsum: inv[row] = 1 / sum(P[row,:])
//   stage4: out = P V (NT, B=V^T); epilogue scales row r by inv[r]
// ---------------------------------------------------------------------------

#define B_  4
#define S_  2048
#define DIN 1024
#define DQ  1024
#define DV  1024

#define BM 128
#define BN 128
#define BKH 64                 // halves per k-tile: 128B smem rows
#define NT 256
#define NSTAGE 3
#define STAGE_BYTES 32768      // A tile 16KB + B tile 16KB
#define SMEM_TOTAL  (NSTAGE * STAGE_BYTES)   // 96KB -> 2 CTAs/SM
#define TSTR 136               // vT staging stride (halves)
#define EXP_OFF 6.0f           // exp offset (cancels via inv-sum)

// -------------------- scratch (allocation-free rule) -----------------------
__device__ __half g_xh[3][(size_t)B_ * S_ * DIN];
__device__ __half g_wh[3][(size_t)DQ * DIN];
__device__ __half g_qh[(size_t)B_ * S_ * DQ];
__device__ __half g_kh[(size_t)B_ * S_ * DQ];
__device__ __half g_vTh[(size_t)DV * B_ * S_];   // [dv][batch][s]
__device__ __half g_ph[(size_t)B_ * S_ * S_];    // un-normalized exp weights
__device__ float  g_inv[(size_t)B_ * S_];        // 1 / row sum

// ------------------------------- helpers -----------------------------------
__device__ __forceinline__ uint32_t smem_u32(const void* p) {
    uint32_t a;
    asm("{ .reg .u64 t; cvta.to.shared.u64 t, %1; cvt.u32.u64 %0, t; }" : "=r"(a) : "l"(p));
    return a;
}
__device__ __forceinline__ void cpa16(uint32_t dst, const void* src) {
    asm volatile("cp.async.cg.shared.global [%0], [%1], 16;" :: "r"(dst), "l"(src));
}
__device__ __forceinline__ void cpcommit() { asm volatile("cp.async.commit_group;"); }
__device__ __forceinline__ void cpwait0() { asm volatile("cp.async.wait_group 0;"); }
__device__ __forceinline__ void cpwait1() { asm volatile("cp.async.wait_group 1;"); }

__device__ __forceinline__ void ldsm4(uint32_t* r, uint32_t addr) {
    asm volatile("ldmatrix.sync.aligned.m8n8.x4.shared.b16 {%0,%1,%2,%3}, [%4];"
                 : "=r"(r[0]), "=r"(r[1]), "=r"(r[2]), "=r"(r[3]) : "r"(addr));
}
__device__ __forceinline__ void mma16(float* c, const uint32_t* a, uint32_t b0, uint32_t b1) {
    asm volatile(
        "mma.sync.aligned.m16n8k16.row.col.f32.f16.f16.f32 "
        "{%0,%1,%2,%3}, {%4,%5,%6,%7}, {%8,%9}, {%0,%1,%2,%3};"
        : "+f"(c[0]), "+f"(c[1]), "+f"(c[2]), "+f"(c[3])
        : "r"(a[0]), "r"(a[1]), "r"(a[2]), "r"(a[3]), "r"(b0), "r"(b1));
}

// ------------------------------- GEMM ---------------------------------------
struct HArgs {
    const __half* A[3];
    const __half* Bm[3];
    const float*  bias[3];
    void*         C[3];
    const int*    mask;
    const float*  rinv;
    int lda, ldb, K;
    long long aS, bS, cS, mS;
    float scale;
};

enum { E_PROJ = 0, E_SCORES = 1, E_OUT = 2 };

template <int EPI>
__global__ __launch_bounds__(NT, 2)
void hgemm(HArgs g)
{
    extern __shared__ char smem[];
    const uint32_t sb = smem_u32(smem);
    const int tid = threadIdx.x;
    const int z   = blockIdx.z;

    const __half* Ap;
    const __half* Bp;
    if (EPI == E_PROJ) { Ap = g.A[z]; Bp = g.Bm[z]; }
    else {
        Ap = g.A[0]  + (size_t)z * g.aS;
        Bp = g.Bm[0] + (size_t)z * g.bS;
    }
    const int lda = g.lda, ldb = g.ldb, K = g.K;
    const int row0 = blockIdx.y * BM;
    const int col0 = blockIdx.x * BN;
    const int n = K / BKH;

    const int lane = tid & 31, warp = tid >> 5;
    const int gr = lane >> 2, tg = lane & 3;
    const int wm0 = (warp & 1) * 64;    // warp tile 64 (m) x 32 (n)
    const int wn0 = (warp >> 1) * 32;

    // ldmatrix per-lane bases
    const int mi = lane >> 3, l7 = lane & 7;
    const int arow0 = wm0 + (mi & 1) * 8 + l7;
    const int asel  = mi >> 1;
    const int ar7   = arow0 & 7;
    const int brow0 = wn0 + (mi >> 1) * 8 + l7;
    const int bsel  = mi & 1;
    const int br7   = brow0 & 7;

    float acc[4][4][4];
    #pragma unroll
    for (int i = 0; i < 4; i++)
        #pragma unroll
        for (int j = 0; j < 4; j++)
            #pragma unroll
            for (int r = 0; r < 4; r++) acc[i][j][r] = 0.0f;

    auto loadTile = [&](int k0, int st) {
        uint32_t da = sb + st * STAGE_BYTES;
        uint32_t db = da + 16384;
        #pragma unroll
        for (int t = 0; t < 4; t++) {
            int idx = tid + t * NT;
            int r = idx >> 3, ch = idx & 7;
            cpa16(da + r * 128 + ((ch ^ (r & 7)) << 4),
                  Ap + (size_t)(row0 + r) * lda + k0 + ch * 8);
        }
        #pragma unroll
        for (int t = 0; t < 4; t++) {
            int idx = tid + t * NT;
            int r = idx >> 3, ch = idx & 7;
            cpa16(db + r * 128 + ((ch ^ (r & 7)) << 4),
                  Bp + (size_t)(col0 + r) * ldb + k0 + ch * 8);
        }
        cpcommit();
    };

    // prologue: 2 stages in flight
    loadTile(0, 0);
    if (n > 1) loadTile(BKH, 1);

    for (int it = 0; it < n; it++) {
        const int cur = it % NSTAGE;
        if (it + 1 < n) cpwait1(); else cpwait0();
        __syncthreads();

        // issue next-next stage loads first: copies fly under the MMAs
        if (it + 2 < n) loadTile((it + 2) * BKH, (it + 2) % NSTAGE);

        const uint32_t da = sb + cur * STAGE_BYTES;
        const uint32_t db = da + 16384;
        #pragma unroll
        for (int ks = 0; ks < 4; ks++) {
            uint32_t af[4][4], bf[2][4];
            #pragma unroll
            for (int mb = 0; mb < 4; mb++)
                ldsm4(af[mb], da + (uint32_t)(arow0 + 16 * mb) * 128
                              + (((ks * 2 + asel) ^ ar7) << 4));
            #pragma unroll
            for (int jp = 0; jp < 2; jp++)
                ldsm4(bf[jp], db + (uint32_t)(brow0 + 16 * jp) * 128
                              + (((ks * 2 + bsel) ^ br7) << 4));
            #pragma unroll
            for (int i = 0; i < 4; i++)
                #pragma unroll
                for (int j = 0; j < 4; j++)
                    mma16(acc[i][j], af[i], bf[j >> 1][(j & 1) * 2],
                          bf[j >> 1][(j & 1) * 2 + 1]);
        }
    }
    __syncthreads();   // all compute done before any smem reuse below

    // ------------------------------ epilogue -------------------------------
    if (EPI == E_PROJ) {
        const float* biasp = g.bias[z];
        if (z < 2) {
            __half* Cq = (__half*)g.C[z];
            #pragma unroll
            for (int i = 0; i < 4; i++) {
                int r = row0 + wm0 + i * 16 + gr;
                #pragma unroll
                for (int j = 0; j < 4; j++) {
                    int c = col0 + wn0 + j * 8 + tg * 2;
                    float bx = biasp[c], by = biasp[c + 1];
                    *(half2*)&Cq[(size_t)r * DQ + c] =
                        __floats2half2_rn(acc[i][j][0] + bx, acc[i][j][1] + by);
                    *(half2*)&Cq[(size_t)(r + 8) * DQ + c] =
                        __floats2half2_rn(acc[i][j][2] + bx, acc[i][j][3] + by);
                }
            }
        } else {
            // V^T: stage fp16 tile in smem, write transposed (token-contiguous)
            __half* ts = (__half*)smem;
            #pragma unroll
            for (int i = 0; i < 4; i++) {
                int r = wm0 + i * 16 + gr;
                #pragma unroll
                for (int j = 0; j < 4; j++) {
                    int c = wn0 + j * 8 + tg * 2;
                    float bx = biasp[col0 + c], by = biasp[col0 + c + 1];
                    *(half2*)&ts[r * TSTR + c] =
                        __floats2half2_rn(acc[i][j][0] + bx, acc[i][j][1] + by);
                    *(half2*)&ts[(r + 8) * TSTR + c] =
                        __floats2half2_rn(acc[i][j][2] + bx, acc[i][j][3] + by);
                }
            }
            __syncthreads();
            const int cc = tid & 127, seg = tid >> 7;
            const int gc = col0 + cc;
            const int batch = row0 >> 11, s0 = row0 & 2047;
            __half* vT = (__half*)g.C[2];
            size_t base = ((size_t)gc * B_ + batch) * S_ + s0 + seg * 64;
            #pragma unroll
            for (int r0 = 0; r0 < 64; r0 += 8) {
                __half h[8];
                #pragma unroll
                for (int t = 0; t < 8; t++)
                    h[t] = ts[(seg * 64 + r0 + t) * TSTR + cc];
                *(uint4*)&vT[base + r0] = *(uint4*)h;
            }
        }
    } else if (EPI == E_SCORES) {
        // e = mask ? 0 : exp(s*scale - EXP_OFF), stored fp16 (un-normalized)
        __half* Pp = (__half*)g.C[0] + (size_t)z * g.cS;
        const int* maskp = g.mask + (size_t)z * g.mS;
        const float sc = g.scale;
        #pragma unroll
        for (int i = 0; i < 4; i++) {
            int r = row0 + wm0 + i * 16 + gr;
            #pragma unroll
            for (int j = 0; j < 4; j++) {
                int c = col0 + wn0 + j * 8 + tg * 2;
                int2 m0 = *(const int2*)&maskp[(size_t)r * S_ + c];
                int2 m1 = *(const int2*)&maskp[(size_t)(r + 8) * S_ + c];
                float e00 = m0.x ? 0.0f : __expf(fmaf(acc[i][j][0], sc, -EXP_OFF));
                float e01 = m0.y ? 0.0f : __expf(fmaf(acc[i][j][1], sc, -EXP_OFF));
                float e10 = m1.x ? 0.0f : __expf(fmaf(acc[i][j][2], sc, -EXP_OFF));
                float e11 = m1.y ? 0.0f : __expf(fmaf(acc[i][j][3], sc, -EXP_OFF));
                *(half2*)&Pp[(size_t)r * S_ + c]       = __floats2half2_rn(e00, e01);
                *(half2*)&Pp[(size_t)(r + 8) * S_ + c] = __floats2half2_rn(e10, e11);
            }
        }
    } else {
        // out row r scaled by rinv[r]
        float* Cp = (float*)g.C[0] + (size_t)z * g.cS;
        const float* rinv = g.rinv + (size_t)z * S_;
        #pragma unroll
        for (int i = 0; i < 4; i++) {
            int r = row0 + wm0 + i * 16 + gr;
            float v0 = __ldg(&rinv[r]);
            float v1 = __ldg(&rinv[r + 8]);
            #pragma unroll
            for (int j = 0; j < 4; j++) {
                int c = col0 + wn0 + j * 8 + tg * 2;
                *(float2*)&Cp[(size_t)r * DV + c] =
                    make_float2(acc[i][j][0] * v0, acc[i][j][1] * v0);
                *(float2*)&Cp[(size_t)(r + 8) * DV + c] =
                    make_float2(acc[i][j][2] * v1, acc[i][j][3] * v1);
            }
        }
    }
}

// ------------------------- fp32 -> fp16 conversion --------------------------
__global__ __launch_bounds__(256)
void f2h3_k(__half* __restrict__ dst, const float* __restrict__ s0,
            const float* __restrict__ s1, const float* __restrict__ s2,
            size_t n8)
{
    size_t i = (size_t)blockIdx.x * 256 + threadIdx.x;
    if (i >= n8) return;
    const float* src = (blockIdx.y == 0) ? s0 : (blockIdx.y == 1) ? s1 : s2;
    __half* d = dst + (size_t)blockIdx.y * n8 * 8;
    float4 a = ((const float4*)src)[2 * i];
    float4 b = ((const float4*)src)[2 * i + 1];
    __half h[8];
    h[0] = __float2half_rn(a.x); h[1] = __float2half_rn(a.y);
    h[2] = __float2half_rn(a.z); h[3] = __float2half_rn(a.w);
    h[4] = __float2half_rn(b.x); h[5] = __float2half_rn(b.y);
    h[6] = __float2half_rn(b.z); h[7] = __float2half_rn(b.w);
    ((uint4*)d)[i] = *(uint4*)h;
}

// --------------------------- row inverse sums -------------------------------
__global__ __launch_bounds__(256)
void rowinv_k(const __half* __restrict__ P, float* __restrict__ inv)
{
    size_t row = (size_t)blockIdx.y * S_ + blockIdx.x;
    const __half* p = P + row * S_;
    const int tid = threadIdx.x;

    uint4 u = ((const uint4*)p)[tid];
    const __half* h = (const __half*)&u;
    float s = 0.0f;
    #pragma unroll
    for (int t = 0; t < 8; t++) s += __half2float(h[t]);

    #pragma unroll
    for (int o = 16; o > 0; o >>= 1) s += __shfl_xor_sync(~0u, s, o);
    __shared__ float red[8];
    if ((tid & 31) == 0) red[tid >> 5] = s;
    __syncthreads();
    if (tid == 0) {
        float tot = 0.0f;
        #pragma unroll
        for (int w = 0; w < 8; w++) tot += red[w];
        inv[row] = (tot > 0.0f) ? 1.0f / tot : 0.0f;
    }
}

// ------------------------------ launcher ------------------------------------
extern "C" void kernel_launch(void* const* d_in, const int* in_sizes, int n_in,
                              void* d_out, int out_size)
{
    const float* query = (const float*)d_in[0];
    const float* key   = (const float*)d_in[1];
    const float* value = (const float*)d_in[2];
    const int*   mask  = (const int*)d_in[3];
    const float* Wq    = (const float*)d_in[4];
    const float* bq    = (const float*)d_in[5];
    const float* Wk    = (const float*)d_in[6];
    const float* bk    = (const float*)d_in[7];
    const float* Wv    = (const float*)d_in[8];
    const float* bv    = (const float*)d_in[9];
    float*       out   = (float*)d_out;

    __half *xh, *wh, *qh, *kh, *vTh, *ph;
    float  *ivp;
    cudaGetSymbolAddress((void**)&xh,  g_xh);
    cudaGetSymbolAddress((void**)&wh,  g_wh);
    cudaGetSymbolAddress((void**)&qh,  g_qh);
    cudaGetSymbolAddress((void**)&kh,  g_kh);
    cudaGetSymbolAddress((void**)&vTh, g_vTh);
    cudaGetSymbolAddress((void**)&ph,  g_ph);
    cudaGetSymbolAddress((void**)&ivp, g_inv);

    cudaFuncSetAttribute(hgemm<E_PROJ>,   cudaFuncAttributeMaxDynamicSharedMemorySize, SMEM_TOTAL);
    cudaFuncSetAttribute(hgemm<E_SCORES>, cudaFuncAttributeMaxDynamicSharedMemorySize, SMEM_TOTAL);
    cudaFuncSetAttribute(hgemm<E_OUT>,    cudaFuncAttributeMaxDynamicSharedMemorySize, SMEM_TOTAL);

    const size_t NX = (size_t)B_ * S_ * DIN;   // 8M
    const size_t NW = (size_t)DQ * DIN;        // 1M

    // fp16 conversions: inputs (3x) and weights (3x), one launch each
    f2h3_k<<<dim3((unsigned)(NX / 8 / 256), 3), 256>>>(xh, query, key, value, NX / 8);
    f2h3_k<<<dim3((unsigned)(NW / 8 / 256), 3), 256>>>(wh, Wq, Wk, Wv, NW / 8);

    // stage 1: projections (M fused over batches; z selects q/k/v)
    HArgs pa{};
    pa.A[0] = xh;          pa.A[1] = xh + NX;    pa.A[2] = xh + 2 * NX;
    pa.Bm[0] = wh;         pa.Bm[1] = wh + NW;   pa.Bm[2] = wh + 2 * NW;
    pa.bias[0] = bq;       pa.bias[1] = bk;      pa.bias[2] = bv;
    pa.C[0] = qh;          pa.C[1] = kh;         pa.C[2] = vTh;
    pa.lda = DIN; pa.ldb = DIN; pa.K = DIN;
    hgemm<E_PROJ><<<dim3(DQ / BN, (B_ * S_) / BM, 3), NT, SMEM_TOTAL>>>(pa);

    // stage 2: scores GEMM with fused exp/mask epilogue -> P (fp16)
    HArgs sa{};
    sa.A[0] = qh; sa.Bm[0] = kh; sa.C[0] = ph; sa.mask = mask;
    sa.lda = DQ; sa.ldb = DQ; sa.K = DQ;
    sa.aS = (long long)S_ * DQ; sa.bS = (long long)S_ * DQ;
    sa.cS = (long long)S_ * S_; sa.mS = (long long)S_ * S_;
    sa.scale = 1.0f / sqrtf((float)DQ);
    hgemm<E_SCORES><<<dim3(S_ / BN, S_ / BM, B_), NT, SMEM_TOTAL>>>(sa);

    // row inverse sums
    rowinv_k<<<dim3(S_, B_), 256>>>(ph, ivp);

    // stage 4: out = P @ V (NT, B = V^T); epilogue scales by rinv
    HArgs va{};
    va.A[0] = ph; va.Bm[0] = vTh; va.C[0] = out; va.rinv = ivp;
    va.lda = S_; va.ldb = B_ * S_; va.K = S_;
    va.aS = (long long)S_ * S_; va.bS = S_;
    va.cS = (long long)S_ * DV;
    hgemm<E_OUT><<<dim3(DV / BN, S_ / BM, B_), NT, SMEM_TOTAL>>>(va);
}